// round 9
// baseline (speedup 1.0000x reference)
#include <cuda_runtime.h>

// Two-kernel pipeline:
//  A) corr_kernel: 49-offset wraparound correlation -> g_scratch[49][slots].
//     432 equal-work blocks (256 px x 64 ch). Each thread computes TWO
//     x-adjacent pixels so the 7-tap f2 windows merge into aligned LDS.64 pairs
//     (58 smem wavefronts per 64px-channel vs 100 scalar).
//  B) conv_kernel: 1x1 conv (49->192) as an smem GEMM: corr[49][128] + w[49][192]
//     staged in dynamic smem, 8px x 4d register tile per thread, packed f32x2 FMA.

#define SL 110592   // 65536 (L1) + 2*16384 (L2 parts) + 3*4096 (L3 parts)
__device__ float g_scratch[49 * SL];

__device__ __forceinline__ void cp_async4(void* s, const void* g) {
    unsigned sa = (unsigned)__cvta_generic_to_shared(s);
    asm volatile("cp.async.ca.shared.global [%0], [%1], 4;\n" :: "r"(sa), "l"(g));
}
__device__ __forceinline__ void cp_async16(void* s, const void* g) {
    unsigned sa = (unsigned)__cvta_generic_to_shared(s);
    asm volatile("cp.async.ca.shared.global [%0], [%1], 16;\n" :: "r"(sa), "l"(g));
}
__device__ __forceinline__ void cp_commit() { asm volatile("cp.async.commit_group;\n" ::: "memory"); }
__device__ __forceinline__ void cp_wait0()  { asm volatile("cp.async.wait_group 0;\n" ::: "memory"); }
__device__ __forceinline__ void cp_wait1()  { asm volatile("cp.async.wait_group 1;\n" ::: "memory"); }

// ---------------- Kernel A: correlation, 2 px per thread ----------------
#define A_NT 128
#define CC 4
#define F2W 38
#define F2H 14              // 8 + 6
#define F1C (CC*8*32)       // 1024 floats
#define F2C (CC*F2H*F2W)    // 2128 floats
#define ABUF (F1C + F2C)    // 3152
#define NCH (64/CC)         // 16

template<int H, int W>
__device__ __forceinline__ void corr_block(
    const float* __restrict__ f1, const float* __restrict__ f2,
    int x0, int y0, int slot0, float scale, float* sbuf, int* off2s)
{
    const int tid = threadIdx.x;
    const int tx = tid & 15;        // 16 threads * 2px = 32-wide tile
    const int ty = tid >> 4;        // 8 rows
    const int HW = H * W;

    // one-time wraparound offset table for the f2 halo chunk (channel-local)
    for (int idx = tid; idx < F2C; idx += A_NT) {
        int c   = idx / (F2H * F2W);
        int rem = idx - c * (F2H * F2W);
        int r   = rem / F2W;
        int col = rem - r * F2W;
        int gr = y0 + r - 3;   if (gr < 0) gr += H; if (gr >= H) gr -= H;
        int gc = x0 + col - 3; if (gc < 0) gc += W; if (gc >= W) gc -= W;
        off2s[idx] = (c * H + gr) * W + gc;
    }
    __syncthreads();

    const float* f1t = f1 + y0 * W + x0;
    auto prefetch = [&](int c0, float* buf) {
#pragma unroll
        for (int j = 0; j < 2; j++) {            // f1: 256 float4
            int idx = tid + j * A_NT;
            int c = idx >> 6, rem = idx & 63;
            int r = rem >> 3, c4 = rem & 7;
            cp_async16(buf + idx * 4, f1t + (size_t)(c0 + c) * HW + r * W + c4 * 4);
        }
        float* f2b = buf + F1C;
        const float* f2c0 = f2 + (size_t)c0 * HW;
#pragma unroll
        for (int j = 0; j < 17; j++) {           // f2: 2128 scalars
            int idx = tid + j * A_NT;
            if (j < 16 || idx < F2C)
                cp_async4(f2b + idx, f2c0 + off2s[idx]);
        }
        cp_commit();
    };

    float corr0[49], corr1[49];
#pragma unroll
    for (int k = 0; k < 49; k++) { corr0[k] = 0.0f; corr1[k] = 0.0f; }

    prefetch(0, sbuf);
    prefetch(CC, sbuf + ABUF);

#pragma unroll 1
    for (int i = 0; i < NCH; i++) {
        if (i + 1 < NCH) cp_wait1(); else cp_wait0();
        __syncthreads();
        const float* buf = sbuf + (i & 1) * ABUF;
        const float* f1s = buf;
        const float* f2s = buf + F1C;
#pragma unroll
        for (int c = 0; c < CC; c++) {
            const float2 f1v = *(const float2*)&f1s[c * 256 + ty * 32 + 2 * tx];
            const float* f2c = f2s + c * (F2H * F2W);
#pragma unroll
            for (int iy = 0; iy < 7; iy++) {
                // dy = iy-3 -> halo row ty+6-iy; window cols [2tx, 2tx+7], aligned
                const float* row = f2c + (ty + 6 - iy) * F2W + 2 * tx;
                float2 a = *(const float2*)&row[0];
                float2 bq = *(const float2*)&row[2];
                float2 cq = *(const float2*)&row[4];
                float2 dq = *(const float2*)&row[6];
                const float wa[8] = {a.x, a.y, bq.x, bq.y, cq.x, cq.y, dq.x, dq.y};
#pragma unroll
                for (int ix = 0; ix < 7; ix++) {
                    corr0[iy * 7 + ix] = fmaf(f1v.x, wa[6 - ix], corr0[iy * 7 + ix]);
                    corr1[iy * 7 + ix] = fmaf(f1v.y, wa[7 - ix], corr1[iy * 7 + ix]);
                }
            }
        }
        __syncthreads();
        if (i + 2 < NCH) prefetch((i + 2) * CC, sbuf + (i & 1) * ABUF);
    }

    const int slot = slot0 + (y0 + ty) * W + x0 + 2 * tx;
#pragma unroll
    for (int k = 0; k < 49; k++) {
        float2 v = make_float2(corr0[k] * scale, corr1[k] * scale);
        *(float2*)&g_scratch[(size_t)k * SL + slot] = v;
    }
}

// 432 equal-work blocks: L1 256 | L2 128 (2 c-parts) | L3 48 (3 c-parts)
__global__ void __launch_bounds__(A_NT, 4)
corr_kernel(const float* __restrict__ l1, const float* __restrict__ l2,
            const float* __restrict__ l3)
{
    __shared__ __align__(16) float sbuf[2 * ABUF];
    __shared__ int off2s[F2C];
    const int b = blockIdx.x;
    if (b < 256) {
        int img = b >> 6, t = b & 63;                   // 4x16 tiles
        int x0 = (t & 3) * 32, y0 = (t >> 2) * 8;
        const float* f1 = l1 + (size_t)img * 64 * 16384;
        const float* f2 = l1 + (size_t)(img + 2) * 64 * 16384;
        corr_block<128, 128>(f1, f2, x0, y0, img * 16384, 0.125f, sbuf, off2s);
    } else if (b < 384) {
        int q = b - 256;
        int img = q >> 5, r = q & 31;
        int part = r >> 4, t = r & 15;                  // 2x8 tiles
        int x0 = (t & 1) * 32, y0 = (t >> 1) * 8;
        const float* f1 = l2 + ((size_t)img * 128 + part * 64) * 4096;
        const float* f2 = l2 + ((size_t)(img + 2) * 128 + part * 64) * 4096;
        corr_block<64, 64>(f1, f2, x0, y0, 65536 + part * 16384 + img * 4096,
                           0.08838834764831845f, sbuf, off2s);
    } else {
        int q = b - 384;
        int img = q / 12, r = q - img * 12;
        int part = r >> 2, t = r & 3;                   // 1x4 tiles
        int y0 = t * 8;
        const float* f1 = l3 + ((size_t)img * 192 + part * 64) * 1024;
        const float* f2 = l3 + ((size_t)(img + 2) * 192 + part * 64) * 1024;
        corr_block<32, 32>(f1, f2, 0, y0, 98304 + part * 4096 + img * 1024,
                           0.07216878364870323f, sbuf, off2s);
    }
}

// ---------------- Kernel B: 1x1 conv as smem GEMM ----------------
#define B_NT 128
// dynamic smem layout (floats): w[49*192]=9408 | bias[192] | corr_s[49*128]=6272
#define WS_OFF   0
#define BS_OFF   9408
#define CS_OFF   9600
#define DYN_FLOATS 15872     // 63488 bytes

__device__ __forceinline__ void ffma2(unsigned long long& d, unsigned long long a,
                                      unsigned long long b) {
    asm("fma.rn.f32x2 %0, %1, %2, %0;" : "+l"(d) : "l"(a), "l"(b));
}
__device__ __forceinline__ unsigned long long pack2(float v) {
    unsigned long long r;
    asm("mov.b64 %0, {%1, %1};" : "=l"(r) : "r"(__float_as_uint(v)));
    return r;
}
union U2 { unsigned long long u; float2 f; };

template<int HW>
__device__ __forceinline__ void conv_gemm(const float* __restrict__ dyn,
                                          float* __restrict__ outp, int tid)
{
    const int dg  = tid & 7;     // 8 d-groups * 4 d
    const int pxg = tid >> 3;    // 16 px-groups * 8 px
    const float* wsp = dyn + WS_OFF;
    const float* bsp = dyn + BS_OFF;
    const float* cs  = dyn + CS_OFF + pxg * 8;

#pragma unroll 1
    for (int pass = 0; pass < 6; pass++) {
        const int d0 = pass * 32 + dg * 4;
        float4 bb = *(const float4*)&bsp[d0];
        unsigned long long acc[4][4];
#pragma unroll
        for (int p = 0; p < 4; p++) {
            acc[p][0] = pack2(bb.x); acc[p][1] = pack2(bb.y);
            acc[p][2] = pack2(bb.z); acc[p][3] = pack2(bb.w);
        }
#pragma unroll 7
        for (int k = 0; k < 49; k++) {
            ulonglong2 cA = *(const ulonglong2*)&cs[k * 128];       // px 0..3
            ulonglong2 cB = *(const ulonglong2*)&cs[k * 128 + 4];   // px 4..7
            float4 wv = *(const float4*)&wsp[k * 192 + d0];
            unsigned long long w0 = pack2(wv.x), w1 = pack2(wv.y);
            unsigned long long w2 = pack2(wv.z), w3 = pack2(wv.w);
            ffma2(acc[0][0], cA.x, w0); ffma2(acc[0][1], cA.x, w1);
            ffma2(acc[0][2], cA.x, w2); ffma2(acc[0][3], cA.x, w3);
            ffma2(acc[1][0], cA.y, w0); ffma2(acc[1][1], cA.y, w1);
            ffma2(acc[1][2], cA.y, w2); ffma2(acc[1][3], cA.y, w3);
            ffma2(acc[2][0], cB.x, w0); ffma2(acc[2][1], cB.x, w1);
            ffma2(acc[2][2], cB.x, w2); ffma2(acc[2][3], cB.x, w3);
            ffma2(acc[3][0], cB.y, w0); ffma2(acc[3][1], cB.y, w1);
            ffma2(acc[3][2], cB.y, w2); ffma2(acc[3][3], cB.y, w3);
        }
#pragma unroll
        for (int dd = 0; dd < 4; dd++) {
            U2 u0, u1, u2, u3;
            u0.u = acc[0][dd]; u1.u = acc[1][dd];
            u2.u = acc[2][dd]; u3.u = acc[3][dd];
            float* o = outp + (size_t)(d0 + dd) * HW + pxg * 8;
            *(float4*)&o[0] = make_float4(u0.f.x, u0.f.y, u1.f.x, u1.f.y);
            *(float4*)&o[4] = make_float4(u2.f.x, u2.f.y, u3.f.x, u3.f.y);
        }
    }
}

__global__ void __launch_bounds__(B_NT)
conv_kernel(const float* __restrict__ w1, const float* __restrict__ b1,
            const float* __restrict__ w2, const float* __restrict__ b2,
            const float* __restrict__ w3, const float* __restrict__ b3,
            float* __restrict__ out)
{
    extern __shared__ __align__(16) float dyn[];
    const int tid = threadIdx.x;
    const int b = blockIdx.x;

    const float *wsrc, *bsrc;
    if (b < 512)      { wsrc = w1; bsrc = b1; }
    else if (b < 640) { wsrc = w2; bsrc = b2; }
    else              { wsrc = w3; bsrc = b3; }

    // stage w (2352 float4) + bias (48 float4) asynchronously
#pragma unroll
    for (int j = 0; j < 19; j++) {
        if (j < 18 || tid < (2400 - 18 * B_NT)) {
            int idx = tid + j * B_NT;
            const float4* src = (idx < 2352) ? ((const float4*)wsrc + idx)
                                             : ((const float4*)bsrc + (idx - 2352));
            cp_async16(dyn + idx * 4, src);
        }
    }
    cp_commit();

    // stage corr tile [49][128] (sum channel-parts for L2/L3), overlaps cp.async
    float* cs = dyn + CS_OFF;
    float* outp;
    if (b < 512) {
        const int px0 = b * B_NT;
#pragma unroll
        for (int j = 0; j < 13; j++) {
            int f4i = tid + j * B_NT;
            if (j < 12 || f4i < 1568) {
                int k = f4i >> 5, o = (f4i & 31) * 4;
                float4 v = *(const float4*)&g_scratch[(size_t)k * SL + px0 + o];
                *(float4*)&cs[k * 128 + o] = v;
            }
        }
        int img = b >> 7, pix = px0 & 16383;
        outp = out + (size_t)img * 192 * 16384 + pix;
    } else if (b < 640) {
        const int local0 = b * B_NT - 65536;
#pragma unroll
        for (int j = 0; j < 13; j++) {
            int f4i = tid + j * B_NT;
            if (j < 12 || f4i < 1568) {
                int k = f4i >> 5, o = (f4i & 31) * 4;
                const float* s = &g_scratch[(size_t)k * SL + local0 + o];
                float4 u = *(const float4*)&s[65536];
                float4 v = *(const float4*)&s[81920];
                *(float4*)&cs[k * 128 + o] =
                    make_float4(u.x + v.x, u.y + v.y, u.z + v.z, u.w + v.w);
            }
        }
        int img = local0 >> 12, pix = local0 & 4095;
        outp = out + 12582912u + (size_t)img * 192 * 4096 + pix;
    } else {
        const int local0 = b * B_NT - 81920;
#pragma unroll
        for (int j = 0; j < 13; j++) {
            int f4i = tid + j * B_NT;
            if (j < 12 || f4i < 1568) {
                int k = f4i >> 5, o = (f4i & 31) * 4;
                const float* s = &g_scratch[(size_t)k * SL + local0 + o];
                float4 u = *(const float4*)&s[98304];
                float4 v = *(const float4*)&s[102400];
                float4 w = *(const float4*)&s[106496];
                *(float4*)&cs[k * 128 + o] =
                    make_float4(u.x + v.x + w.x, u.y + v.y + w.y,
                                u.z + v.z + w.z, u.w + v.w + w.w);
            }
        }
        int img = local0 >> 10, pix = local0 & 1023;
        outp = out + 15728640u + (size_t)img * 192 * 1024 + pix;
    }

    cp_wait0();
    __syncthreads();

    if (b < 512)      conv_gemm<16384>(dyn, outp, tid);
    else if (b < 640) conv_gemm<4096>(dyn, outp, tid);
    else              conv_gemm<1024>(dyn, outp, tid);
}

extern "C" void kernel_launch(void* const* d_in, const int* in_sizes, int n_in,
                              void* d_out, int out_size) {
    const float* l1 = (const float*)d_in[0];
    const float* l2 = (const float*)d_in[1];
    const float* l3 = (const float*)d_in[2];
    const float* w1 = (const float*)d_in[3];
    const float* b1 = (const float*)d_in[4];
    const float* w2 = (const float*)d_in[5];
    const float* b2 = (const float*)d_in[6];
    const float* w3 = (const float*)d_in[7];
    const float* b3 = (const float*)d_in[8];
    float* out = (float*)d_out;

    cudaFuncSetAttribute((const void*)corr_kernel,
                         cudaFuncAttributePreferredSharedMemoryCarveout, 100);
    cudaFuncSetAttribute((const void*)conv_kernel,
                         cudaFuncAttributePreferredSharedMemoryCarveout, 100);
    cudaFuncSetAttribute((const void*)conv_kernel,
                         cudaFuncAttributeMaxDynamicSharedMemorySize,
                         DYN_FLOATS * sizeof(float));

    corr_kernel<<<432, A_NT>>>(l1, l2, l3);
    conv_kernel<<<672, B_NT, DYN_FLOATS * sizeof(float)>>>(w1, b1, w2, b2, w3, b3, out);
}

// round 11
// speedup vs baseline: 1.7570x; 1.7570x over previous
#include <cuda_runtime.h>

// Two-kernel pipeline, both math paths in packed fma.rn.f32x2 (2 px per thread):
//  A) corr_kernel: 49-offset wraparound correlation -> g_scratch[49][slots].
//     432 equal-work blocks (256 px x 64 ch). Packed accumulator {px0,px1};
//     f2 halo rows padded to 40 floats starting at x0-4 so staging is pure
//     float4 cp.async (wrap handled at float4 granularity; W % 4 == 0).
//  B) conv_kernel: 1x1 conv (49->192) with broadcast weights in smem,
//     2 px x 96 d per thread (d split across 2 blocks), packed f32x2 FMA.

#define SL 110592   // 65536 (L1) + 2*16384 (L2 parts) + 3*4096 (L3 parts)
__device__ float g_scratch[49 * SL];

__device__ __forceinline__ void cp_async16(void* s, const void* g) {
    unsigned sa = (unsigned)__cvta_generic_to_shared(s);
    asm volatile("cp.async.ca.shared.global [%0], [%1], 16;\n" :: "r"(sa), "l"(g));
}
__device__ __forceinline__ void cp_commit() { asm volatile("cp.async.commit_group;\n" ::: "memory"); }
__device__ __forceinline__ void cp_wait0()  { asm volatile("cp.async.wait_group 0;\n" ::: "memory"); }
__device__ __forceinline__ void cp_wait1()  { asm volatile("cp.async.wait_group 1;\n" ::: "memory"); }

typedef unsigned long long u64;
__device__ __forceinline__ void ffma2(u64& d, u64 a, u64 b) {
    asm("fma.rn.f32x2 %0, %1, %2, %0;" : "+l"(d) : "l"(a), "l"(b));
}
__device__ __forceinline__ u64 pk(float lo, float hi) {
    u64 r;
    asm("mov.b64 %0, {%1, %2};" : "=l"(r) : "f"(lo), "f"(hi));
    return r;
}
union U2 { u64 u; float2 f; };

// ---------------- Kernel A: correlation ----------------
#define A_NT 128
#define CC 4
#define F2W 40              // halo row: cols x0-4 .. x0+35 (float4-aligned)
#define F2H 14
#define NOFF (F2H * 10)     // 140 wrapped float4 offsets
#define F1C (CC*8*32)       // 1024 floats
#define F2C (CC*F2H*F2W)    // 2240 floats
#define F2C4 (F2C/4)        // 560 float4
#define ABUF (F1C + F2C)    // 3264
#define NCH (64/CC)         // 16

template<int H, int W>
__device__ __forceinline__ void corr_block(
    const float* __restrict__ f1, const float* __restrict__ f2,
    int x0, int y0, int slot0, float scale, float* sbuf, int* off2s)
{
    const int tid = threadIdx.x;
    const int tx = tid & 15;        // 16 threads * 2px = 32-wide tile
    const int ty = tid >> 4;        // 8 rows
    const int HW = H * W;

    // per-(row, float4) wrapped gmem offsets for the f2 halo (channel-local).
    // NOTE: NOFF=140 > A_NT=128, so this MUST be a strided loop (R10 bug).
    for (int idx = tid; idx < NOFF; idx += A_NT) {
        int r = idx / 10, q = idx - r * 10;
        int gr = y0 + r - 3;     if (gr < 0) gr += H; if (gr >= H) gr -= H;
        int gc = x0 - 4 + q * 4; if (gc < 0) gc += W; if (gc >= W) gc -= W;
        off2s[idx] = gr * W + gc;
    }
    __syncthreads();

    const float* f1t = f1 + y0 * W + x0;
    auto prefetch = [&](int c0, float* buf) {
#pragma unroll
        for (int j = 0; j < 2; j++) {            // f1: 256 float4
            int idx = tid + j * A_NT;
            int c = idx >> 6, rem = idx & 63;
            int r = rem >> 3, q = rem & 7;
            cp_async16(buf + idx * 4, f1t + (size_t)(c0 + c) * HW + r * W + q * 4);
        }
        float* f2b = buf + F1C;
#pragma unroll
        for (int j = 0; j < 5; j++) {            // f2: 560 float4
            int idx = tid + j * A_NT;
            if (j < 4 || idx < F2C4) {
                int c = idx / 140, rem = idx - c * 140;
                cp_async16(f2b + idx * 4, f2 + (size_t)(c0 + c) * HW + off2s[rem]);
            }
        }
        cp_commit();
    };

    u64 acc[49];
#pragma unroll
    for (int k = 0; k < 49; k++) acc[k] = 0ull;

    prefetch(0, sbuf);
    prefetch(CC, sbuf + ABUF);

#pragma unroll 1
    for (int i = 0; i < NCH; i++) {
        if (i + 1 < NCH) cp_wait1(); else cp_wait0();
        __syncthreads();
        const float* buf = sbuf + (i & 1) * ABUF;
        const float* f1s = buf;
        const float* f2s = buf + F1C;
#pragma unroll
        for (int c = 0; c < CC; c++) {
            const float2 f1v = *(const float2*)&f1s[c * 256 + ty * 32 + 2 * tx];
            const u64 f1p = pk(f1v.x, f1v.y);
            const float* f2c = f2s + c * (F2H * F2W);
#pragma unroll
            for (int iy = 0; iy < 7; iy++) {
                // dy = iy-3 -> halo row ty+6-iy; taps for px pair (2tx+p):
                // halo col j = 2tx + p + 7 - ix  (halo starts at gmem col x0-4)
                const float2* row = (const float2*)(f2c + (ty + 6 - iy) * F2W) + tx;
                float2 e0 = row[0], e1 = row[1], e2 = row[2], e3 = row[3], e4 = row[4];
                const int k0 = iy * 7;
                ffma2(acc[k0 + 0], f1p, pk(e3.y, e4.x));   // {7,8}
                ffma2(acc[k0 + 1], f1p, pk(e3.x, e3.y));   // {6,7}
                ffma2(acc[k0 + 2], f1p, pk(e2.y, e3.x));   // {5,6}
                ffma2(acc[k0 + 3], f1p, pk(e2.x, e2.y));   // {4,5}
                ffma2(acc[k0 + 4], f1p, pk(e1.y, e2.x));   // {3,4}
                ffma2(acc[k0 + 5], f1p, pk(e1.x, e1.y));   // {2,3}
                ffma2(acc[k0 + 6], f1p, pk(e0.y, e1.x));   // {1,2}
            }
        }
        __syncthreads();
        if (i + 2 < NCH) prefetch((i + 2) * CC, sbuf + (i & 1) * ABUF);
    }

    const int slot = slot0 + (y0 + ty) * W + x0 + 2 * tx;
#pragma unroll
    for (int k = 0; k < 49; k++) {
        U2 u; u.u = acc[k];
        float2 v = make_float2(u.f.x * scale, u.f.y * scale);
        *(float2*)&g_scratch[(size_t)k * SL + slot] = v;
    }
}

// 432 equal-work blocks: L1 256 | L2 128 (2 c-parts) | L3 48 (3 c-parts)
__global__ void __launch_bounds__(A_NT, 4)
corr_kernel(const float* __restrict__ l1, const float* __restrict__ l2,
            const float* __restrict__ l3)
{
    __shared__ __align__(16) float sbuf[2 * ABUF];
    __shared__ int off2s[NOFF];
    const int b = blockIdx.x;
    if (b < 256) {
        int img = b >> 6, t = b & 63;                   // 4x16 tiles of 32x8
        int x0 = (t & 3) * 32, y0 = (t >> 2) * 8;
        const float* f1 = l1 + (size_t)img * 64 * 16384;
        const float* f2 = l1 + (size_t)(img + 2) * 64 * 16384;
        corr_block<128, 128>(f1, f2, x0, y0, img * 16384, 0.125f, sbuf, off2s);
    } else if (b < 384) {
        int q = b - 256;
        int img = q >> 5, r = q & 31;
        int part = r >> 4, t = r & 15;                  // 2x8 tiles
        int x0 = (t & 1) * 32, y0 = (t >> 1) * 8;
        const float* f1 = l2 + ((size_t)img * 128 + part * 64) * 4096;
        const float* f2 = l2 + ((size_t)(img + 2) * 128 + part * 64) * 4096;
        corr_block<64, 64>(f1, f2, x0, y0, 65536 + part * 16384 + img * 4096,
                           0.08838834764831845f, sbuf, off2s);
    } else {
        int q = b - 384;
        int img = q / 12, r = q - img * 12;
        int part = r >> 2, t = r & 3;                   // 1x4 tiles
        int y0 = t * 8;
        const float* f1 = l3 + ((size_t)img * 192 + part * 64) * 1024;
        const float* f2 = l3 + ((size_t)(img + 2) * 192 + part * 64) * 1024;
        corr_block<32, 32>(f1, f2, 0, y0, 98304 + part * 4096 + img * 1024,
                           0.07216878364870323f, sbuf, off2s);
    }
}

// ---------------- Kernel B: 1x1 conv, 2px x 96d per thread ----------------
#define B_NT 128
// smem: ws[49][96] + bias[96] = 4800 floats = 19.2KB (static)
#define BS_OFF 4704

template<int HW>
__device__ __forceinline__ void conv_gemm(const float2* __restrict__ corrp,
                                          const float* __restrict__ ws,
                                          float* __restrict__ outp)
{
#pragma unroll 1
    for (int pass = 0; pass < 24; pass++) {
        const int d0 = pass * 4;
        float2 bi01 = *(const float2*)&ws[BS_OFF + d0];
        float2 bi23 = *(const float2*)&ws[BS_OFF + d0 + 2];
        u64 A01 = pk(bi01.x, bi01.y);   // px0: {d0, d0+1}
        u64 A23 = pk(bi23.x, bi23.y);   // px0: {d0+2, d0+3}
        u64 B01 = A01, B23 = A23;       // px1
#pragma unroll
        for (int k = 0; k < 49; k++) {
            float4 wv = *(const float4*)&ws[k * 96 + d0];    // broadcast LDS.128
            u64 w01 = pk(wv.x, wv.y);
            u64 w23 = pk(wv.z, wv.w);
            float2 cc = corrp[k];
            u64 c0 = pk(cc.x, cc.x);
            u64 c1 = pk(cc.y, cc.y);
            ffma2(A01, c0, w01); ffma2(A23, c0, w23);
            ffma2(B01, c1, w01); ffma2(B23, c1, w23);
        }
        U2 a01, a23, b01, b23;
        a01.u = A01; a23.u = A23; b01.u = B01; b23.u = B23;
        *(float2*)&outp[(size_t)(d0 + 0) * HW] = make_float2(a01.f.x, b01.f.x);
        *(float2*)&outp[(size_t)(d0 + 1) * HW] = make_float2(a01.f.y, b01.f.y);
        *(float2*)&outp[(size_t)(d0 + 2) * HW] = make_float2(a23.f.x, b23.f.x);
        *(float2*)&outp[(size_t)(d0 + 3) * HW] = make_float2(a23.f.y, b23.f.y);
    }
}

// 672 blocks: (pxblk, dhalf) pairs. L1: 512 | L2: 128 | L3: 32
__global__ void __launch_bounds__(B_NT, 4)
conv_kernel(const float* __restrict__ w1, const float* __restrict__ b1,
            const float* __restrict__ w2, const float* __restrict__ b2,
            const float* __restrict__ w3, const float* __restrict__ b3,
            float* __restrict__ out)
{
    __shared__ __align__(16) float ws[49 * 96 + 96];
    const int tid = threadIdx.x;
    const int b = blockIdx.x;

    int pxblk, dhalf, lvl;
    const float *wsrc, *bsrc;
    if (b < 512)      { pxblk = b >> 1;          dhalf = b & 1; lvl = 0; wsrc = w1; bsrc = b1; }
    else if (b < 640) { int q = b - 512; pxblk = q >> 1; dhalf = q & 1; lvl = 1; wsrc = w2; bsrc = b2; }
    else              { int q = b - 640; pxblk = q >> 1; dhalf = q & 1; lvl = 2; wsrc = w3; bsrc = b3; }

    // stage this d-half of w (49 x 24 float4) + bias (24 float4)
#pragma unroll
    for (int j = 0; j < 10; j++) {
        int idx = tid + j * B_NT;
        if (j < 9 || idx < 1200) {
            if (idx < 1176) {
                int k = idx / 24, q = idx - k * 24;
                cp_async16(ws + k * 96 + q * 4, wsrc + k * 192 + dhalf * 96 + q * 4);
            } else {
                int q = idx - 1176;
                cp_async16(ws + BS_OFF + q * 4, bsrc + dhalf * 96 + q * 4);
            }
        }
    }
    cp_commit();

    // load corr px pair (sum channel-parts for L2/L3); overlaps cp.async
    const int p0 = pxblk * 256 + tid * 2;     // local px within level
    float2 corrp[49];
    float* outp;
    if (lvl == 0) {
#pragma unroll
        for (int k = 0; k < 49; k++)
            corrp[k] = *(const float2*)&g_scratch[(size_t)k * SL + p0];
        int img = p0 >> 14, pix = p0 & 16383;
        outp = out + (size_t)img * 192 * 16384 + (size_t)dhalf * 96 * 16384 + pix;
    } else if (lvl == 1) {
#pragma unroll
        for (int k = 0; k < 49; k++) {
            float2 u = *(const float2*)&g_scratch[(size_t)k * SL + 65536 + p0];
            float2 v = *(const float2*)&g_scratch[(size_t)k * SL + 81920 + p0];
            corrp[k] = make_float2(u.x + v.x, u.y + v.y);
        }
        int img = p0 >> 12, pix = p0 & 4095;
        outp = out + 12582912u + (size_t)img * 192 * 4096 + (size_t)dhalf * 96 * 4096 + pix;
    } else {
#pragma unroll
        for (int k = 0; k < 49; k++) {
            float2 u = *(const float2*)&g_scratch[(size_t)k * SL +  98304 + p0];
            float2 v = *(const float2*)&g_scratch[(size_t)k * SL + 102400 + p0];
            float2 w = *(const float2*)&g_scratch[(size_t)k * SL + 106496 + p0];
            corrp[k] = make_float2(u.x + v.x + w.x, u.y + v.y + w.y);
        }
        int img = p0 >> 10, pix = p0 & 1023;
        outp = out + 15728640u + (size_t)img * 192 * 1024 + (size_t)dhalf * 96 * 1024 + pix;
    }

    cp_wait0();
    __syncthreads();

    if (lvl == 0)      conv_gemm<16384>(corrp, ws, outp);
    else if (lvl == 1) conv_gemm<4096>(corrp, ws, outp);
    else               conv_gemm<1024>(corrp, ws, outp);
}

extern "C" void kernel_launch(void* const* d_in, const int* in_sizes, int n_in,
                              void* d_out, int out_size) {
    const float* l1 = (const float*)d_in[0];
    const float* l2 = (const float*)d_in[1];
    const float* l3 = (const float*)d_in[2];
    const float* w1 = (const float*)d_in[3];
    const float* b1 = (const float*)d_in[4];
    const float* w2 = (const float*)d_in[5];
    const float* b2 = (const float*)d_in[6];
    const float* w3 = (const float*)d_in[7];
    const float* b3 = (const float*)d_in[8];
    float* out = (float*)d_out;

    cudaFuncSetAttribute((const void*)corr_kernel,
                         cudaFuncAttributePreferredSharedMemoryCarveout, 100);
    cudaFuncSetAttribute((const void*)conv_kernel,
                         cudaFuncAttributePreferredSharedMemoryCarveout, 100);

    corr_kernel<<<432, A_NT>>>(l1, l2, l3);
    conv_kernel<<<672, B_NT>>>(w1, b1, w2, b2, w3, b3, out);
}